// round 1
// baseline (speedup 1.0000x reference)
#include <cuda_runtime.h>
#include <cuda_bf16.h>
#include <cstdint>

// Problem constants (fixed by the dataset generator)
#define BATCH 512
#define SEQ   2048
#define TAGS  32
#define START_IDX 30
#define STOP_IDX  31

// Scratch for per-batch partial results (device globals: allocation-free)
__device__ float g_logZ[BATCH];
__device__ float g_score[BATCH];

// ---------------------------------------------------------------------------
// Forward algorithm in probability domain.
// One warp per batch. Lane j carries alpha[j] = exp(fv[j] - C).
// Lane i caches expT[i][j] = exp(trans[i][j]) for all j in registers.
// Step: t_i = sum_j alpha_j * expT[i][j]   (32 shfl + 32 fma)
//       alpha_i' = exp(feat_i) * t_i
// Renormalize by lane 0's value every 4 steps; C accumulates log2(scale).
// ---------------------------------------------------------------------------
__global__ void __launch_bounds__(128, 1)
crf_forward_kernel(const float* __restrict__ feats,
                   const float* __restrict__ trans)
{
    const unsigned FULL = 0xffffffffu;
    int warp = (blockIdx.x * blockDim.x + threadIdx.x) >> 5;
    int lane = threadIdx.x & 31;
    if (warp >= BATCH) return;

    // Per-lane row of exp(transitions): row[j] = exp(trans[lane][j]).
    // exp(-10000) underflows to exactly 0 -> blocked transitions drop out.
    float row[TAGS];
#pragma unroll
    for (int j = 0; j < TAGS; j++) {
        row[j] = __expf(__ldg(trans + lane * TAGS + j));
    }
    // Terminal weights: exp(trans[STOP][lane])
    float expStop = __expf(__ldg(trans + STOP_IDX * TAGS + lane));

    // alpha init: exp(fv_init - 0) with fv_init = 0 at START, -1e4 elsewhere
    float p = (lane == START_IDX) ? 1.0f : 0.0f;
    float Clog2 = 0.0f;

    const size_t base = (size_t)warp * SEQ * TAGS + lane;

    // Prefetch ring, distance 8 (8 * ~105 cyc > 577-cyc DRAM latency)
    float fb[8];
#pragma unroll
    for (int k = 0; k < 8; k++) fb[k] = feats[base + (size_t)k * TAGS];

    for (int s0 = 0; s0 < SEQ; s0 += 8) {
#pragma unroll
        for (int u = 0; u < 8; u++) {
            const int s = s0 + u;
            const float f = fb[u];
            // refill prefetch slot (predicated off for the tail)
            const int sp = s + 8;
            if (sp < SEQ) fb[u] = feats[base + (size_t)sp * TAGS];

            const float EF = __expf(f);   // off critical path (dep on old load)

            // dense matvec across lanes: 32 shfl + 32 fma, 4 accumulators
            float t0 = 0.f, t1 = 0.f, t2 = 0.f, t3 = 0.f;
#pragma unroll
            for (int j = 0; j < TAGS; j += 4) {
                t0 = fmaf(__shfl_sync(FULL, p, j + 0), row[j + 0], t0);
                t1 = fmaf(__shfl_sync(FULL, p, j + 1), row[j + 1], t1);
                t2 = fmaf(__shfl_sync(FULL, p, j + 2), row[j + 2], t2);
                t3 = fmaf(__shfl_sync(FULL, p, j + 3), row[j + 3], t3);
            }
            const float sv = ((t0 + t1) + (t2 + t3)) * EF;

            if ((u & 3) == 3) {
                // renormalize by lane 0's value (strictly > 0 for s >= 1)
                const float s0v = __shfl_sync(FULL, sv, 0);
                p = __fdividef(sv, s0v);       // rcp.approx + mul
                Clog2 += __log2f(s0v);         // off critical path
            } else {
                p = sv;
            }
        }
    }

    // Terminal: logZ = C + log(sum_i alpha_i * exp(trans[STOP][i]))
    float v = p * expStop;
#pragma unroll
    for (int o = 16; o; o >>= 1) v += __shfl_xor_sync(FULL, v, o);

    if (lane == 0) {
        g_logZ[warp] = (Clog2 + __log2f(v)) * 0.6931471805599453f;
    }
}

// ---------------------------------------------------------------------------
// Gold-path score: sum_s trans[tag_s, tag_{s-1}] + feat[b,s,tag_s]
//                  (+ stop transition), tag_{-1} = START.
// One warp per batch, lanes stride over s.
// ---------------------------------------------------------------------------
__global__ void __launch_bounds__(128, 1)
crf_score_kernel(const float* __restrict__ feats,
                 const float* __restrict__ trans,
                 const int*   __restrict__ tags)
{
    const unsigned FULL = 0xffffffffu;
    __shared__ float st[TAGS * TAGS];
    for (int i = threadIdx.x; i < TAGS * TAGS; i += blockDim.x)
        st[i] = trans[i];
    __syncthreads();

    int warp = (blockIdx.x * blockDim.x + threadIdx.x) >> 5;
    int lane = threadIdx.x & 31;
    if (warp >= BATCH) return;

    const int* tg = tags + (size_t)warp * SEQ;
    const size_t fbase = (size_t)warp * SEQ * TAGS;

    float sum = 0.0f;
    for (int s = lane; s < SEQ; s += 32) {
        const int t  = tg[s];
        const int tp = (s == 0) ? START_IDX : tg[s - 1];
        sum += st[t * TAGS + tp] + feats[fbase + (size_t)s * TAGS + t];
    }
#pragma unroll
    for (int o = 16; o; o >>= 1) sum += __shfl_xor_sync(FULL, sum, o);

    if (lane == 0) {
        sum += st[STOP_IDX * TAGS + tg[SEQ - 1]];
        g_score[warp] = sum;
    }
}

// ---------------------------------------------------------------------------
// Deterministic final reduction: out = sum_b (logZ_b - score_b)
// ---------------------------------------------------------------------------
__global__ void __launch_bounds__(512, 1)
crf_reduce_kernel(float* __restrict__ out)
{
    __shared__ float sh[BATCH];
    const int i = threadIdx.x;
    sh[i] = g_logZ[i] - g_score[i];
    __syncthreads();
#pragma unroll
    for (int o = BATCH / 2; o > 0; o >>= 1) {
        if (i < o) sh[i] += sh[i + o];
        __syncthreads();
    }
    if (i == 0) out[0] = sh[0];
}

// ---------------------------------------------------------------------------
extern "C" void kernel_launch(void* const* d_in, const int* in_sizes, int n_in,
                              void* d_out, int out_size)
{
    (void)in_sizes; (void)n_in; (void)out_size;
    const float* feats = (const float*)d_in[0];   // [512, 2048, 32] f32
    const float* trans = (const float*)d_in[1];   // [32, 32] f32
    const int*   tags  = (const int*)d_in[2];     // [512, 2048] i32
    float* out = (float*)d_out;                   // scalar f32

    // 512 warps total: 128 blocks x 4 warps -> <=1 block/SM, ~1 warp/SMSP
    crf_forward_kernel<<<BATCH / 4, 128>>>(feats, trans);
    crf_score_kernel<<<BATCH / 4, 128>>>(feats, trans, tags);
    crf_reduce_kernel<<<1, BATCH>>>(out);
}

// round 2
// speedup vs baseline: 1.0990x; 1.0990x over previous
#include <cuda_runtime.h>
#include <cuda_bf16.h>
#include <cstdint>

#define BATCH 512
#define SEQ   2048
#define TAGS  32
#define START_IDX 30
#define STOP_IDX  31

// per-batch (logZ - score), reduced by final kernel
__device__ float g_val[BATCH];

// ---------------------------------------------------------------------------
// Fused forward algorithm + gold-path score. One warp per batch.
// Probability domain: lane j carries q_j with invariant exp(fv_j) = q_j * 2^C.
// Per step, q is broadcast through shared memory (STS + syncwarp + 8x LDS.128),
// each lane i computes EF_i/q0 * sum_j exp(trans[i][j]) * q_j.
// Renormalization (divide by q0, accumulate log2(q0)) is off the critical path.
// ---------------------------------------------------------------------------

struct StepState {
    float p;        // this lane's q value
    float Clog2;    // accumulated log2 normalizers
    float sc;       // fused gold score partial
    int   prevt;    // previous gold tag
};

__global__ void __launch_bounds__(64, 1)
crf_fused_kernel(const float* __restrict__ feats,
                 const float* __restrict__ trans,
                 const int*   __restrict__ tags)
{
    const unsigned FULL = 0xffffffffu;
    __shared__ float st[TAGS * TAGS];                    // raw transitions (score path)
    __shared__ __align__(16) float bc[2][2][TAGS];       // [warpInBlk][parity][32]

    const int tid  = threadIdx.x;
    const int w    = tid >> 5;
    const int lane = tid & 31;
    const int warp = blockIdx.x * 2 + w;

    for (int i = tid; i < TAGS * TAGS; i += 64) st[i] = trans[i];
    __syncthreads();

    // exp(transitions) row for this lane; exp(-1e4) == 0 blocks transitions.
    float row[TAGS];
#pragma unroll
    for (int j = 0; j < TAGS; j += 4) {
        const float4 t4 = *(const float4*)(trans + lane * TAGS + j);
        row[j + 0] = __expf(t4.x);
        row[j + 1] = __expf(t4.y);
        row[j + 2] = __expf(t4.z);
        row[j + 3] = __expf(t4.w);
    }
    const float expStop = __expf(trans[STOP_IDX * TAGS + lane]);

    const int*   tg   = tags + (size_t)warp * SEQ;
    const size_t base = (size_t)warp * SEQ * TAGS + lane;

    float* const b0 = bc[w][0];
    float* const b1 = bc[w][1];

    // feats prefetch ring, distance 8
    float fb[8];
#pragma unroll
    for (int k = 0; k < 8; k++) fb[k] = feats[base + (size_t)k * TAGS];

    StepState S;

    // ---- step 0 (alpha known analytically: indicator at START) ----
    {
        const float f = fb[0];
        fb[0] = feats[base + (size_t)8 * TAGS];
        S.p     = __expf(f) * row[START_IDX];
        S.Clog2 = 0.0f;
        const int t = __ldg(tg);
        S.sc    = (lane == t) ? (f + st[t * TAGS + START_IDX]) : 0.0f;
        S.prevt = t;
    }

    // ---- one recurrence step (parity selects double buffer) ----
    auto step = [&](int s, float* wb) __attribute__((always_inline)) {
        const float f = fb[s & 7];
        const int  sp = s + 8;
        if (sp < SEQ) fb[s & 7] = feats[base + (size_t)sp * TAGS];

        const int t = __ldg(tg + s);        // uniform, L1-resident
        const float EF = __expf(f);

        wb[lane] = S.p;                     // STS (broadcast source)
        __syncwarp(FULL);
        const float4 a0 = *(const float4*)(wb + 0);
        const float4 a1 = *(const float4*)(wb + 4);
        const float4 a2 = *(const float4*)(wb + 8);
        const float4 a3 = *(const float4*)(wb + 12);
        const float4 a4 = *(const float4*)(wb + 16);
        const float4 a5 = *(const float4*)(wb + 20);
        const float4 a6 = *(const float4*)(wb + 24);
        const float4 a7 = *(const float4*)(wb + 28);

        // off-critical-path: renorm factor, normalizer log, gold score
        const float m = __fdividef(EF, a0.x);        // MUFU rcp + mul
        S.Clog2 += __log2f(a0.x);
        if (lane == t) S.sc += f + st[t * TAGS + S.prevt];
        S.prevt = t;

        // dense matvec: 32 FMA on 8 accumulators
        float t0 = a0.x * row[0];
        float t1 = a1.x * row[4];
        float t2 = a2.x * row[8];
        float t3 = a3.x * row[12];
        float t4 = a4.x * row[16];
        float t5 = a5.x * row[20];
        float t6 = a6.x * row[24];
        float t7 = a7.x * row[28];
        t0 = fmaf(a0.y, row[1],  t0); t0 = fmaf(a0.z, row[2],  t0); t0 = fmaf(a0.w, row[3],  t0);
        t1 = fmaf(a1.y, row[5],  t1); t1 = fmaf(a1.z, row[6],  t1); t1 = fmaf(a1.w, row[7],  t1);
        t2 = fmaf(a2.y, row[9],  t2); t2 = fmaf(a2.z, row[10], t2); t2 = fmaf(a2.w, row[11], t2);
        t3 = fmaf(a3.y, row[13], t3); t3 = fmaf(a3.z, row[14], t3); t3 = fmaf(a3.w, row[15], t3);
        t4 = fmaf(a4.y, row[17], t4); t4 = fmaf(a4.z, row[18], t4); t4 = fmaf(a4.w, row[19], t4);
        t5 = fmaf(a5.y, row[21], t5); t5 = fmaf(a5.z, row[22], t5); t5 = fmaf(a5.w, row[23], t5);
        t6 = fmaf(a6.y, row[25], t6); t6 = fmaf(a6.z, row[26], t6); t6 = fmaf(a6.w, row[27], t6);
        t7 = fmaf(a7.y, row[29], t7); t7 = fmaf(a7.z, row[30], t7); t7 = fmaf(a7.w, row[31], t7);

        const float sv = (((t0 + t1) + (t2 + t3)) + ((t4 + t5) + (t6 + t7)));
        S.p = sv * m;
    };

    // steps 1..7 (prologue, fully unrolled so ring indices are compile-time)
#pragma unroll
    for (int s = 1; s < 8; s++) step(s, (s & 1) ? b1 : b0);

    // steps 8..2047 (2040 = 8*255, exact)
    for (int s0 = 8; s0 < SEQ; s0 += 8) {
#pragma unroll
        for (int u = 0; u < 8; u++) step(s0 + u, (u & 1) ? b1 : b0);
    }

    // terminal logZ and score reduction
    float v = S.p * expStop;
    float sc = S.sc;
#pragma unroll
    for (int o = 16; o; o >>= 1) {
        v  += __shfl_xor_sync(FULL, v,  o);
        sc += __shfl_xor_sync(FULL, sc, o);
    }

    if (lane == 0) {
        const float logZ  = (S.Clog2 + __log2f(v)) * 0.6931471805599453f;
        const float score = sc + st[STOP_IDX * TAGS + S.prevt];
        g_val[warp] = logZ - score;
    }
}

// ---------------------------------------------------------------------------
// Deterministic final reduction: out = sum_b g_val[b]
// ---------------------------------------------------------------------------
__global__ void __launch_bounds__(512, 1)
crf_reduce_kernel(float* __restrict__ out)
{
    __shared__ float sh[BATCH];
    const int i = threadIdx.x;
    sh[i] = g_val[i];
    __syncthreads();
#pragma unroll
    for (int o = BATCH / 2; o > 0; o >>= 1) {
        if (i < o) sh[i] += sh[i + o];
        __syncthreads();
    }
    if (i == 0) out[0] = sh[0];
}

// ---------------------------------------------------------------------------
extern "C" void kernel_launch(void* const* d_in, const int* in_sizes, int n_in,
                              void* d_out, int out_size)
{
    (void)in_sizes; (void)n_in; (void)out_size;
    const float* feats = (const float*)d_in[0];   // [512, 2048, 32] f32
    const float* trans = (const float*)d_in[1];   // [32, 32] f32
    const int*   tags  = (const int*)d_in[2];     // [512, 2048] i32
    float* out = (float*)d_out;                   // scalar f32

    // 256 blocks x 2 warps: spread warps across SMs to reduce MIO contention
    crf_fused_kernel<<<BATCH / 2, 64>>>(feats, trans, tags);
    crf_reduce_kernel<<<1, BATCH>>>(out);
}